// round 15
// baseline (speedup 1.0000x reference)
#include <cuda_runtime.h>
#include <math.h>

#define NMID 500000
#define DD 64
#define KI 4
#define CC 512
#define SS 256
#define BB 512
#define NEGV (-4294967295.0f)
#define FMIN2 (-3.402823466e38f)

#define IST 68
#define QST 264
#define SST 260
#define SM_FLOATS 51328

typedef unsigned long long u64;

__device__ __forceinline__ u64 splat2(float x) {
    u64 r; asm("mov.b64 %0, {%1,%1};" : "=l"(r) : "f"(x)); return r;
}
__device__ __forceinline__ void ffma2(u64& acc, u64 a, u64 b) {
    asm("fma.rn.f32x2 %0, %1, %2, %0;" : "+l"(acc) : "l"(a), "l"(b));
}
__device__ __forceinline__ float2 unpack2(u64 v) {
    float2 f; asm("mov.b64 {%0,%1}, %2;" : "=f"(f.x), "=f"(f.y) : "l"(v)); return f;
}
__device__ __forceinline__ float tanh_fast(float x) {
    float t = __expf(2.f * x);
    return 1.f - __fdividef(2.f, t + 1.f);
}

__device__ float g_wmean[KI*DD];
__device__ float g_posSum[DD];
__device__ float g_cand0[CC*DD];
__device__ float g_cand[CC*DD];
__device__ float g_candW4[CC*DD];
__device__ float g_transT[(size_t)CC*CC];
__device__ float g_seq[(size_t)BB*SS*DD];
__device__ float g_mean[BB*DD];
__device__ float g_mh[BB*DD];
__device__ float g_L1[(size_t)BB*CC];
__device__ float g_L2[(size_t)BB*CC];

// ---------------- K0 ----------------
__global__ void k_pre(const float* __restrict__ pos) {
    int t = threadIdx.x;
    if (t < KI*DD) g_wmean[t] = 0.f;
    if (t < DD) {
        float s = 0.f;
        for (int i = 0; i < SS; i++) s += pos[i*DD + t];
        g_posSum[t] = s;
    }
}

// ---------------- K1 ----------------
__global__ void k_wmean(const float* __restrict__ E, const float* __restrict__ W2) {
    __shared__ float red[8*256];
    int t = threadIdx.x, l = t & 31, wi = t >> 5;
    int gw = (blockIdx.x*blockDim.x + t) >> 5;
    int TW = (gridDim.x*blockDim.x) >> 5;
    float2 w2[KI];
#pragma unroll
    for (int k = 0; k < KI; k++) {
        w2[k].x = W2[k*DD + 2*l];
        w2[k].y = W2[k*DD + 2*l + 1];
    }
    float2 acc[KI];
#pragma unroll
    for (int k = 0; k < KI; k++) acc[k] = make_float2(0.f, 0.f);
    const float2* E2 = (const float2*)E;
    for (long n = gw; n < NMID; n += TW) {
        float2 e = E2[n*32 + l];
#pragma unroll
        for (int k = 0; k < KI; k++) {
            float p = fmaf(e.x, w2[k].x, e.y*w2[k].y);
#pragma unroll
            for (int o = 16; o; o >>= 1) p += __shfl_xor_sync(~0u, p, o);
            acc[k].x = fmaf(p, e.x, acc[k].x);
            acc[k].y = fmaf(p, e.y, acc[k].y);
        }
    }
#pragma unroll
    for (int k = 0; k < KI; k++) {
        red[wi*256 + k*64 + 2*l]     = acc[k].x;
        red[wi*256 + k*64 + 2*l + 1] = acc[k].y;
    }
    __syncthreads();
    if (t < 256) {
        float s = 0.f;
#pragma unroll
        for (int w = 0; w < 8; w++) s += red[w*256 + t];
        atomicAdd(&g_wmean[t], s);
    }
}

// ---------------- K2 ----------------
__global__ void k_cand(const float* __restrict__ W3, const float* __restrict__ W1,
                       const float* __restrict__ W4) {
    __shared__ float row[DD];
    int d = threadIdx.x, c = blockIdx.x;
    float v = 0.f;
#pragma unroll
    for (int k = 0; k < KI; k++) v = fmaf(W3[k*CC + c], g_wmean[k*DD + d], v);
    row[d] = v;
    g_cand0[c*DD + d] = v;
    __syncthreads();
    float a = 0.f, bv = 0.f;
#pragma unroll 8
    for (int e = 0; e < DD; e++) {
        float r = row[e];
        a  = fmaf(r, W1[e*DD + d], a);
        bv = fmaf(r, W4[e*DD + d], bv);
    }
    g_cand[c*DD + d]   = tanhf(a);
    g_candW4[c*DD + d] = bv;
}

// ---------------- K4a: heavy per-batch part (unchanged) ----------------
__global__ void __launch_bounds__(1024,1) k_heavy(
    const float* __restrict__ E, const float* __restrict__ pos,
    const float* __restrict__ dw, const float* __restrict__ db,
    const int* __restrict__ his, const int* __restrict__ mask)
{
    extern __shared__ float sm[];
    float* itemsS = sm;
    float* qT     = sm + 17408;
    float* sc     = sm + 34304;
    float* maskS  = sm + 50944;
    float* colS   = sm + 51200;
    __shared__ float sDen;

    int b = blockIdx.x, t = threadIdx.x, w = t >> 5, l = t & 31;

    if (t < SS) maskS[t] = (float)mask[b*SS + t];
    if (t < 64) colS[t] = 0.f;
    {
        float* dwS = sc; float* biasS = sc + 4096;
        for (int i = t; i < 4096; i += 1024) dwS[i] = dw[i];
        if (t < 64) biasS[t] = db[t];
    }
    {
        const float4* E4 = (const float4*)E;
        float4* it4 = (float4*)itemsS;
        const int* hr = his + b*SS;
        for (int f = t; f < SS*16; f += 1024) {
            int s = f >> 4, c = f & 15;
            it4[s*17 + c] = E4[(size_t)hr[s]*16 + c];
        }
    }
    __syncthreads();
    if (w == 0) {
        float s = 0.f;
        for (int i = l; i < SS; i += 32) s += maskS[i];
#pragma unroll
        for (int o = 16; o; o >>= 1) s += __shfl_xor_sync(~0u, s, o);
        if (l == 0) sDen = 1.f / (s + 1e-9f);
    }

    {
        float* dwS = sc; float* biasS = sc + 4096;
        int s = t >> 2, q4 = t & 3;
        int d0 = 16*q4;
        u64 acc[8];
#pragma unroll
        for (int i = 0; i < 8; i++) acc[i] = 0ull;
#pragma unroll 4
        for (int e = 0; e < 64; e++) {
            float xe = itemsS[s*IST + e] + pos[s*DD + e];
            u64 xs = splat2(xe);
            const ulonglong2* wp = (const ulonglong2*)&dwS[e*64 + d0];
#pragma unroll
            for (int q = 0; q < 4; q++) {
                ulonglong2 wv = wp[q];
                ffma2(acc[2*q],   xs, wv.x);
                ffma2(acc[2*q+1], xs, wv.y);
            }
        }
#pragma unroll
        for (int i = 0; i < 8; i++) {
            float2 p = unpack2(acc[i]);
            int d = d0 + 2*i;
            qT[d*QST + s]     = tanhf(p.x + biasS[d]);
            qT[(d+1)*QST + s] = tanhf(p.y + biasS[d+1]);
        }
    }
    __syncthreads();

    float rs0 = 0.f, rs1 = 0.f;
    for (int g = 0; g < 4; g++) {
        int s0 = g*64;
        {
            int ty = t >> 7;
            int tx = t & 127;
            u64 acc[4][2];
#pragma unroll
            for (int i = 0; i < 4; i++) { acc[i][0] = 0ull; acc[i][1] = 0ull; }
#pragma unroll 4
            for (int e = 0; e < 64; e++) {
                const float* qe = &qT[e*QST];
                ulonglong2 a01 = *(const ulonglong2*)&qe[s0 + 8*ty];
                ulonglong2 a23 = *(const ulonglong2*)&qe[s0 + 8*ty + 4];
                float2 bf = *(const float2*)&qe[2*tx];
                u64 b0 = splat2(bf.x), b1 = splat2(bf.y);
                ffma2(acc[0][0], a01.x, b0); ffma2(acc[0][1], a01.x, b1);
                ffma2(acc[1][0], a01.y, b0); ffma2(acc[1][1], a01.y, b1);
                ffma2(acc[2][0], a23.x, b0); ffma2(acc[2][1], a23.x, b1);
                ffma2(acc[3][0], a23.y, b0); ffma2(acc[3][1], a23.y, b1);
            }
#pragma unroll
            for (int rp = 0; rp < 4; rp++) {
                float2 c0 = unpack2(acc[rp][0]);
                float2 c1 = unpack2(acc[rp][1]);
                *(float2*)&sc[(8*ty + 2*rp)*SST + 2*tx]     = make_float2(c0.x, c1.x);
                *(float2*)&sc[(8*ty + 2*rp + 1)*SST + 2*tx] = make_float2(c0.y, c1.y);
            }
        }
        __syncthreads();
        for (int rr = w; rr < 64; rr += 32) {
            int s = s0 + rr;
            if (maskS[s] == 0.f) {
                for (int c = l; c < 256; c += 32) sc[rr*SST + c] = 0.f;
            } else {
                float v[8]; float mx = FMIN2;
#pragma unroll
                for (int c = 0; c < 8; c++) {
                    float rawv = sc[rr*SST + l + 32*c] * 0.125f;
                    if (maskS[l + 32*c] == 0.f) rawv = NEGV;
                    v[c] = rawv; mx = fmaxf(mx, rawv);
                }
#pragma unroll
                for (int o = 16; o; o >>= 1) mx = fmaxf(mx, __shfl_xor_sync(~0u, mx, o));
                float sum = 0.f;
#pragma unroll
                for (int c = 0; c < 8; c++) { v[c] = expf(v[c] - mx); sum += v[c]; }
#pragma unroll
                for (int o = 16; o; o >>= 1) sum += __shfl_xor_sync(~0u, sum, o);
                float inv = 1.f / sum;
#pragma unroll
                for (int c = 0; c < 8; c++) sc[rr*SST + l + 32*c] = v[c]*inv;
            }
        }
        __syncthreads();
        {
            int ry = t >> 5;
            int rx = t & 31;
            u64 acc0 = 0ull, acc1 = 0ull;
            const float* r0p = &sc[(2*ry)*SST];
            const float* r1p = &sc[(2*ry + 1)*SST];
#pragma unroll 4
            for (int k = 0; k < 256; k += 2) {
                float2 af0 = *(const float2*)&r0p[k];
                float2 af1 = *(const float2*)&r1p[k];
                u64 bk  = *(const u64*)&itemsS[k*IST + 2*rx];
                u64 bk1 = *(const u64*)&itemsS[(k+1)*IST + 2*rx];
                ffma2(acc0, splat2(af0.x), bk);
                ffma2(acc1, splat2(af1.x), bk);
                ffma2(acc0, splat2(af0.y), bk1);
                ffma2(acc1, splat2(af1.y), bk1);
            }
            float2 u0 = unpack2(acc0), u1 = unpack2(acc1);
            float* so = &g_seq[((size_t)b*SS + s0 + 2*ry)*DD + 2*rx];
            *(float2*)so = u0;
            *(float2*)(so + DD) = u1;
            rs0 += u0.x + u1.x;
            rs1 += u0.y + u1.y;
        }
        __syncthreads();
    }
    {
        int rx = t & 31;
        atomicAdd(&colS[2*rx],   rs0);
        atomicAdd(&colS[2*rx+1], rs1);
    }
    __syncthreads();
    if (t < 64) g_mean[b*64 + t] = (colS[t] + g_posSum[t]) * sDen;
}

// ============ Tiled GEMM kernels (out[i][j] = sum_e A[i][e]*B[j][e]) ============
// 64x64 tile, 256 threads, 4x4 outputs/thread, f32x2 packed over j-pairs.
// Per-output accumulation is e-ascending single-fmaf -> bitwise == GEMV chains.

// trans scores: A=candW4 (i), B=cand0 (j); store to g_transT[j*CC + i]
__global__ void __launch_bounds__(256) k_transmm() {
    __shared__ float AS[64*68];
    __shared__ float BT[64*66];
    int t = threadIdx.x;
    int i0 = blockIdx.x*64, j0 = blockIdx.y*64;
    {
        const float4* Ag = (const float4*)g_candW4;
        float4* AS4 = (float4*)AS;
        for (int idx = t; idx < 1024; idx += 256) {
            int r = idx >> 4, f = idx & 15;
            AS4[r*17 + f] = Ag[(size_t)(i0 + r)*16 + f];
        }
        for (int idx = t; idx < 4096; idx += 256) {
            int e = idx & 63, bb = idx >> 6;
            BT[e*66 + bb] = g_cand0[(size_t)(j0 + bb)*64 + e];
        }
    }
    __syncthreads();
    int iq = t >> 4, jq = t & 15;
    u64 acc[4][2];
#pragma unroll
    for (int i = 0; i < 4; i++) { acc[i][0] = 0ull; acc[i][1] = 0ull; }
#pragma unroll 4
    for (int e4 = 0; e4 < 16; e4++) {
        float avf[16];
#pragma unroll
        for (int i = 0; i < 4; i++) {
            float4 v = *(const float4*)&AS[(iq*4 + i)*68 + e4*4];
            avf[i*4+0]=v.x; avf[i*4+1]=v.y; avf[i*4+2]=v.z; avf[i*4+3]=v.w;
        }
#pragma unroll
        for (int q = 0; q < 4; q++) {
            int e = 4*e4 + q;
            u64 m0 = *(const u64*)&BT[e*66 + jq*4];
            u64 m1 = *(const u64*)&BT[e*66 + jq*4 + 2];
#pragma unroll
            for (int i = 0; i < 4; i++) {
                u64 s = splat2(avf[i*4+q]);
                ffma2(acc[i][0], s, m0);
                ffma2(acc[i][1], s, m1);
            }
        }
    }
#pragma unroll
    for (int i = 0; i < 4; i++) {
        float2 u0 = unpack2(acc[i][0]);
        float2 u1 = unpack2(acc[i][1]);
        int ii = i0 + iq*4 + i;
        int jj = j0 + jq*4;
        g_transT[(size_t)(jj+0)*CC + ii] = u0.x;
        g_transT[(size_t)(jj+1)*CC + ii] = u0.y;
        g_transT[(size_t)(jj+2)*CC + ii] = u1.x;
        g_transT[(size_t)(jj+3)*CC + ii] = u1.y;
    }
}

// softmax over i within each row j of g_transT (identical reduction to old k_trans)
__global__ void __launch_bounds__(256) k_transsm() {
    __shared__ float red[8];
    __shared__ float bmax, bsum;
    int t = threadIdx.x, j = blockIdx.x, w = t >> 5, l = t & 31;
    float v0 = g_transT[(size_t)j*CC + t];
    float v1 = g_transT[(size_t)j*CC + t + 256];
    float m = fmaxf(v0, v1);
#pragma unroll
    for (int o = 16; o; o >>= 1) m = fmaxf(m, __shfl_xor_sync(~0u, m, o));
    if (l == 0) red[w] = m;
    __syncthreads();
    if (t == 0) { float mm = red[0]; for (int i = 1; i < 8; i++) mm = fmaxf(mm, red[i]); bmax = mm; }
    __syncthreads();
    float p0 = expf(v0 - bmax), p1 = expf(v1 - bmax);
    float s = p0 + p1;
#pragma unroll
    for (int o = 16; o; o >>= 1) s += __shfl_xor_sync(~0u, s, o);
    if (l == 0) red[w] = s;
    __syncthreads();
    if (t == 0) { float ss = 0.f; for (int i = 0; i < 8; i++) ss += red[i]; bsum = ss; }
    __syncthreads();
    float inv = 1.f / bsum;
    g_transT[(size_t)j*CC + t]       = p0 * inv;
    g_transT[(size_t)j*CC + t + 256] = p1 * inv;
}

// mh = tanh(mean @ W1): grid 64, 8 b per block
__global__ void __launch_bounds__(512) k_mh(const float* __restrict__ W1) {
    __shared__ float W1S[4096];
    __shared__ float meanS[512];
    int t = threadIdx.x;
    int b0 = blockIdx.x*8;
    for (int i = t; i < 4096; i += 512) W1S[i] = W1[i];
    meanS[t] = g_mean[b0*64 + t];
    __syncthreads();
    int bb = t >> 6, d = t & 63;
    float a = 0.f;
#pragma unroll 16
    for (int e = 0; e < 64; e++) a = fmaf(meanS[bb*64 + e], W1S[e*64 + d], a);
    g_mh[(size_t)(b0 + bb)*64 + d] = tanhf(a);
}

// L1[b][c] = cand[c] . mh[b] : A=g_cand (i=c), B=g_mh (j=b); store g_L1[b*CC + c]
__global__ void __launch_bounds__(256) k_logits1() {
    __shared__ float AS[64*68];
    __shared__ float BT[64*66];
    int t = threadIdx.x;
    int c0 = blockIdx.x*64, b0 = blockIdx.y*64;
    {
        const float4* Ag = (const float4*)g_cand;
        float4* AS4 = (float4*)AS;
        for (int idx = t; idx < 1024; idx += 256) {
            int r = idx >> 4, f = idx & 15;
            AS4[r*17 + f] = Ag[(size_t)(c0 + r)*16 + f];
        }
        for (int idx = t; idx < 4096; idx += 256) {
            int e = idx & 63, bb = idx >> 6;
            BT[e*66 + bb] = g_mh[(size_t)(b0 + bb)*64 + e];
        }
    }
    __syncthreads();
    int iq = t >> 4, jq = t & 15;
    u64 acc[4][2];
#pragma unroll
    for (int i = 0; i < 4; i++) { acc[i][0] = 0ull; acc[i][1] = 0ull; }
#pragma unroll 4
    for (int e4 = 0; e4 < 16; e4++) {
        float avf[16];
#pragma unroll
        for (int i = 0; i < 4; i++) {
            float4 v = *(const float4*)&AS[(iq*4 + i)*68 + e4*4];
            avf[i*4+0]=v.x; avf[i*4+1]=v.y; avf[i*4+2]=v.z; avf[i*4+3]=v.w;
        }
#pragma unroll
        for (int q = 0; q < 4; q++) {
            int e = 4*e4 + q;
            u64 m0 = *(const u64*)&BT[e*66 + jq*4];
            u64 m1 = *(const u64*)&BT[e*66 + jq*4 + 2];
#pragma unroll
            for (int i = 0; i < 4; i++) {
                u64 s = splat2(avf[i*4+q]);
                ffma2(acc[i][0], s, m0);
                ffma2(acc[i][1], s, m1);
            }
        }
    }
#pragma unroll
    for (int i = 0; i < 4; i++) {
        float2 u0 = unpack2(acc[i][0]);
        float2 u1 = unpack2(acc[i][1]);
        int cc = c0 + iq*4 + i;
        int bb = b0 + jq*4;
        g_L1[(size_t)(bb+0)*CC + cc] = u0.x;
        g_L1[(size_t)(bb+1)*CC + cc] = u0.y;
        g_L1[(size_t)(bb+2)*CC + cc] = u1.x;
        g_L1[(size_t)(bb+3)*CC + cc] = u1.y;
    }
}

// L2[b][t] = sum_i transT[t][i] * L1[b][i] : A=g_transT rows t, B=g_L1 rows b, k=512 in 8 chunks
__global__ void __launch_bounds__(256) k_logits2() {
    __shared__ float AS[64*68];
    __shared__ float BT[64*66];
    int t = threadIdx.x;
    int t0 = blockIdx.x*64, b0 = blockIdx.y*64;
    int iq = t >> 4, jq = t & 15;
    u64 acc[4][2];
#pragma unroll
    for (int i = 0; i < 4; i++) { acc[i][0] = 0ull; acc[i][1] = 0ull; }
    for (int ch = 0; ch < 8; ch++) {
        __syncthreads();
        {
            const float4* Ag = (const float4*)g_transT;
            float4* AS4 = (float4*)AS;
            for (int idx = t; idx < 1024; idx += 256) {
                int r = idx >> 4, f = idx & 15;
                AS4[r*17 + f] = Ag[(size_t)(t0 + r)*128 + ch*16 + f];
            }
            for (int idx = t; idx < 4096; idx += 256) {
                int e = idx & 63, bb = idx >> 6;
                BT[e*66 + bb] = g_L1[(size_t)(b0 + bb)*CC + ch*64 + e];
            }
        }
        __syncthreads();
#pragma unroll 4
        for (int e4 = 0; e4 < 16; e4++) {
            float avf[16];
#pragma unroll
            for (int i = 0; i < 4; i++) {
                float4 v = *(const float4*)&AS[(iq*4 + i)*68 + e4*4];
                avf[i*4+0]=v.x; avf[i*4+1]=v.y; avf[i*4+2]=v.z; avf[i*4+3]=v.w;
            }
#pragma unroll
            for (int q = 0; q < 4; q++) {
                int e = 4*e4 + q;
                u64 m0 = *(const u64*)&BT[e*66 + jq*4];
                u64 m1 = *(const u64*)&BT[e*66 + jq*4 + 2];
#pragma unroll
                for (int i = 0; i < 4; i++) {
                    u64 s = splat2(avf[i*4+q]);
                    ffma2(acc[i][0], s, m0);
                    ffma2(acc[i][1], s, m1);
                }
            }
        }
    }
#pragma unroll
    for (int i = 0; i < 4; i++) {
        float2 u0 = unpack2(acc[i][0]);
        float2 u1 = unpack2(acc[i][1]);
        int tt = t0 + iq*4 + i;
        int bb = b0 + jq*4;
        g_L2[(size_t)(bb+0)*CC + tt] = u0.x;
        g_L2[(size_t)(bb+1)*CC + tt] = u0.y;
        g_L2[(size_t)(bb+2)*CC + tt] = u1.x;
        g_L2[(size_t)(bb+3)*CC + tt] = u1.y;
    }
}

// ---------------- K4b: per-batch tail (top4 + multi-interest + outputs) ----------------
__global__ void __launch_bounds__(512) k_tail2(
    const float* __restrict__ E, const float* __restrict__ W1,
    const float* __restrict__ pos, const int* __restrict__ mask,
    const int* __restrict__ midb, float* __restrict__ out, long out_size)
{
    __shared__ float W1S[4096];
    __shared__ float logitsS[512];
    __shared__ float wrS[4*260];
    __shared__ float aqS[256];
    __shared__ float uebS[256];
    __shared__ float maskS[256];
    __shared__ float itemS[64];
    __shared__ float rv[16]; __shared__ int riS[16];
    __shared__ int idxS[4];
    __shared__ float dotS[4]; __shared__ int ridxS;

    int b = blockIdx.x, t = threadIdx.x, w = t >> 5, l = t & 31;

    if (t < SS) maskS[t] = (float)mask[b*SS + t];
    if (t < 64) itemS[t] = E[(size_t)midb[b]*DD + t];
    for (int i = t; i < 4096; i += 512) W1S[i] = W1[i];
    logitsS[t] = g_L2[(size_t)b*CC + t];
    __syncthreads();

    for (int p = 0; p < 4; p++) {
        float bv = logitsS[t]; int bi = t;
#pragma unroll
        for (int o = 16; o; o >>= 1) {
            float ov = __shfl_xor_sync(~0u, bv, o);
            int   oi = __shfl_xor_sync(~0u, bi, o);
            if (ov > bv || (ov == bv && oi < bi)) { bv = ov; bi = oi; }
        }
        if (l == 0) { rv[w] = bv; riS[w] = bi; }
        __syncthreads();
        if (t == 0) {
            float B2 = rv[0]; int BI = riS[0];
            for (int i = 1; i < 16; i++)
                if (rv[i] > B2 || (rv[i] == B2 && riS[i] < BI)) { B2 = rv[i]; BI = riS[i]; }
            idxS[p] = BI; logitsS[BI] = FMIN2;
        }
        __syncthreads();
    }
    if (t < 256) { int k = t >> 6, d = t & 63; aqS[t] = g_cand[(size_t)idxS[k]*64 + d]; }
    __syncthreads();

    // D: multi-interest attention (fast math OK: feeds outputs 0/1 only)
    {
        int s = t >> 1, half = t & 1;
        int d0 = 32*half;
        u64 acc[16];
#pragma unroll
        for (int i = 0; i < 16; i++) acc[i] = 0ull;
        const float4* sr4 = (const float4*)&g_seq[((size_t)b*SS + s)*DD];
        const float4* pp4 = (const float4*)&pos[s*DD];
#pragma unroll 4
        for (int e4 = 0; e4 < 16; e4++) {
            float4 sv = sr4[e4], pv = pp4[e4];
            float xs4[4];
            xs4[0] = sv.x + pv.x; xs4[1] = sv.y + pv.y;
            xs4[2] = sv.z + pv.z; xs4[3] = sv.w + pv.w;
#pragma unroll
            for (int q = 0; q < 4; q++) {
                u64 xs = splat2(xs4[q]);
                const ulonglong2* wp = (const ulonglong2*)&W1S[(4*e4+q)*64 + d0];
#pragma unroll
                for (int r = 0; r < 8; r++) {
                    ulonglong2 wv = wp[r];
                    ffma2(acc[2*r],   xs, wv.x);
                    ffma2(acc[2*r+1], xs, wv.y);
                }
            }
        }
        float ihv[32];
#pragma unroll
        for (int i = 0; i < 16; i++) {
            float2 p = unpack2(acc[i]);
            ihv[2*i]   = tanh_fast(p.x);
            ihv[2*i+1] = tanh_fast(p.y);
        }
        float wv[4];
#pragma unroll
        for (int k = 0; k < 4; k++) {
            float a = 0.f;
            const float* aq = &aqS[k*64 + d0];
#pragma unroll
            for (int i = 0; i < 32; i++) a = fmaf(ihv[i], aq[i], a);
            a += __shfl_xor_sync(~0u, a, 1);
            wv[k] = a;
        }
        if (half == 0) {
            float m = maskS[s];
#pragma unroll
            for (int k = 0; k < 4; k++)
                wrS[k*260 + s] = (m == 0.f) ? NEGV : wv[k];
        }
    }
    __syncthreads();
    if (w < 4) {
        float v[8]; float mx = FMIN2;
#pragma unroll
        for (int c = 0; c < 8; c++) { v[c] = wrS[w*260 + l + 32*c]; mx = fmaxf(mx, v[c]); }
#pragma unroll
        for (int o = 16; o; o >>= 1) mx = fmaxf(mx, __shfl_xor_sync(~0u, mx, o));
        float sum = 0.f;
#pragma unroll
        for (int c = 0; c < 8; c++) { v[c] = __expf(v[c] - mx); sum += v[c]; }
#pragma unroll
        for (int o = 16; o; o >>= 1) sum += __shfl_xor_sync(~0u, sum, o);
        float inv = 1.f / sum;
#pragma unroll
        for (int c = 0; c < 8; c++) wrS[w*260 + l + 32*c] = v[c]*inv;
    }
    __syncthreads();
    if (t < 256) {
        int k = t >> 6, d = t & 63;
        const float* wp = &wrS[k*260];
        const float* sp = &g_seq[(size_t)b*SS*DD + d];
        float a = 0.f;
#pragma unroll 8
        for (int s = 0; s < 256; s++) a = fmaf(wp[s], sp[(size_t)s*64], a);
        uebS[t] = a;
        long off = 32768 + (long)b*256 + t;
        if (off < out_size) out[off] = a;
    }
    __syncthreads();
    if (w < 4) {
        float p = uebS[w*64 + l]*itemS[l] + uebS[w*64 + l + 32]*itemS[l + 32];
#pragma unroll
        for (int o = 16; o; o >>= 1) p += __shfl_xor_sync(~0u, p, o);
        if (l == 0) dotS[w] = p;
    }
    __syncthreads();
    if (t == 0) {
        float bv2 = dotS[0]; int bi2 = 0;
        for (int k = 1; k < 4; k++) if (dotS[k] > bv2) { bv2 = dotS[k]; bi2 = k; }
        ridxS = bi2;
    }
    __syncthreads();
    if (t < 64) {
        long off = (long)b*64 + t;
        if (off < out_size) out[off] = uebS[ridxS*64 + t];
    }
    if (t < 4) {
        long off = 163840 + (long)b*4 + t;
        if (off < out_size) out[off] = (float)idxS[t];
    }
}

extern "C" void kernel_launch(void* const* d_in, const int* in_sizes, int n_in,
                              void* d_out, int out_size) {
    const float* E    = (const float*)d_in[0];
    const float* W1   = (const float*)d_in[1];
    const float* W2   = (const float*)d_in[2];
    const float* W3   = (const float*)d_in[3];
    const float* W4   = (const float*)d_in[4];
    const float* pos  = (const float*)d_in[5];
    const float* dw   = (const float*)d_in[6];
    const float* db   = (const float*)d_in[7];
    const int*   his  = (const int*)d_in[8];
    const int*   mask = (const int*)d_in[9];
    const int*   midb = (const int*)d_in[10];
    float* out = (float*)d_out;

    cudaFuncSetAttribute(k_heavy, cudaFuncAttributeMaxDynamicSharedMemorySize,
                         SM_FLOATS * (int)sizeof(float));

    k_pre<<<1, 256>>>(pos);
    k_wmean<<<1184, 256>>>(E, W2);
    k_cand<<<CC, DD>>>(W3, W1, W4);
    k_heavy<<<BB, 1024, SM_FLOATS * sizeof(float)>>>(E, pos, dw, db, his, mask);
    k_transmm<<<dim3(8,8), 256>>>();
    k_transsm<<<CC, 256>>>();
    k_mh<<<64, 512>>>(W1);
    k_logits1<<<dim3(8,8), 256>>>();
    k_logits2<<<dim3(8,8), 256>>>();
    k_tail2<<<BB, 512>>>(E, W1, pos, mask, midb, out, (long)out_size);
}

// round 16
// speedup vs baseline: 1.0026x; 1.0026x over previous
#include <cuda_runtime.h>
#include <math.h>

#define NMID 500000
#define DD 64
#define KI 4
#define CC 512
#define SS 256
#define BB 512
#define NEGV (-4294967295.0f)
#define FMIN2 (-3.402823466e38f)

#define IST 68
#define QST 264
#define SST 260
#define SM_FLOATS 51328

typedef unsigned long long u64;

__device__ __forceinline__ u64 splat2(float x) {
    u64 r; asm("mov.b64 %0, {%1,%1};" : "=l"(r) : "f"(x)); return r;
}
__device__ __forceinline__ void ffma2(u64& acc, u64 a, u64 b) {
    asm("fma.rn.f32x2 %0, %1, %2, %0;" : "+l"(acc) : "l"(a), "l"(b));
}
__device__ __forceinline__ float2 unpack2(u64 v) {
    float2 f; asm("mov.b64 {%0,%1}, %2;" : "=f"(f.x), "=f"(f.y) : "l"(v)); return f;
}
__device__ __forceinline__ float tanh_fast(float x) {
    float t = __expf(2.f * x);
    return 1.f - __fdividef(2.f, t + 1.f);
}

__device__ float g_wmean[KI*DD];
__device__ float g_posSum[DD];
__device__ float g_cand0[CC*DD];
__device__ float g_cand[CC*DD];
__device__ float g_candW4[CC*DD];
__device__ float g_transT[(size_t)CC*CC];
__device__ float g_seq[(size_t)BB*SS*DD];
__device__ float g_mean[BB*DD];
__device__ float g_mh[BB*DD];
__device__ float g_L1[(size_t)BB*CC];
__device__ float g_L2[(size_t)BB*CC];

// ---------------- K0 ----------------
__global__ void k_pre(const float* __restrict__ pos) {
    int t = threadIdx.x;
    if (t < KI*DD) g_wmean[t] = 0.f;
    if (t < DD) {
        float s = 0.f;
        for (int i = 0; i < SS; i++) s += pos[i*DD + t];
        g_posSum[t] = s;
    }
}

// ---------------- K1 ----------------
__global__ void k_wmean(const float* __restrict__ E, const float* __restrict__ W2) {
    __shared__ float red[8*256];
    int t = threadIdx.x, l = t & 31, wi = t >> 5;
    int gw = (blockIdx.x*blockDim.x + t) >> 5;
    int TW = (gridDim.x*blockDim.x) >> 5;
    float2 w2[KI];
#pragma unroll
    for (int k = 0; k < KI; k++) {
        w2[k].x = W2[k*DD + 2*l];
        w2[k].y = W2[k*DD + 2*l + 1];
    }
    float2 acc[KI];
#pragma unroll
    for (int k = 0; k < KI; k++) acc[k] = make_float2(0.f, 0.f);
    const float2* E2 = (const float2*)E;
    for (long n = gw; n < NMID; n += TW) {
        float2 e = E2[n*32 + l];
#pragma unroll
        for (int k = 0; k < KI; k++) {
            float p = fmaf(e.x, w2[k].x, e.y*w2[k].y);
#pragma unroll
            for (int o = 16; o; o >>= 1) p += __shfl_xor_sync(~0u, p, o);
            acc[k].x = fmaf(p, e.x, acc[k].x);
            acc[k].y = fmaf(p, e.y, acc[k].y);
        }
    }
#pragma unroll
    for (int k = 0; k < KI; k++) {
        red[wi*256 + k*64 + 2*l]     = acc[k].x;
        red[wi*256 + k*64 + 2*l + 1] = acc[k].y;
    }
    __syncthreads();
    if (t < 256) {
        float s = 0.f;
#pragma unroll
        for (int w = 0; w < 8; w++) s += red[w*256 + t];
        atomicAdd(&g_wmean[t], s);
    }
}

// ---------------- K2 ----------------
__global__ void k_cand(const float* __restrict__ W3, const float* __restrict__ W1,
                       const float* __restrict__ W4) {
    __shared__ float row[DD];
    int d = threadIdx.x, c = blockIdx.x;
    float v = 0.f;
#pragma unroll
    for (int k = 0; k < KI; k++) v = fmaf(W3[k*CC + c], g_wmean[k*DD + d], v);
    row[d] = v;
    g_cand0[c*DD + d] = v;
    __syncthreads();
    float a = 0.f, bv = 0.f;
#pragma unroll 8
    for (int e = 0; e < DD; e++) {
        float r = row[e];
        a  = fmaf(r, W1[e*DD + d], a);
        bv = fmaf(r, W4[e*DD + d], bv);
    }
    g_cand[c*DD + d]   = tanhf(a);
    g_candW4[c*DD + d] = bv;
}

// ---------------- K4a: heavy per-batch part (unchanged) ----------------
__global__ void __launch_bounds__(1024,1) k_heavy(
    const float* __restrict__ E, const float* __restrict__ pos,
    const float* __restrict__ dw, const float* __restrict__ db,
    const int* __restrict__ his, const int* __restrict__ mask)
{
    extern __shared__ float sm[];
    float* itemsS = sm;
    float* qT     = sm + 17408;
    float* sc     = sm + 34304;
    float* maskS  = sm + 50944;
    float* colS   = sm + 51200;
    __shared__ float sDen;

    int b = blockIdx.x, t = threadIdx.x, w = t >> 5, l = t & 31;

    if (t < SS) maskS[t] = (float)mask[b*SS + t];
    if (t < 64) colS[t] = 0.f;
    {
        float* dwS = sc; float* biasS = sc + 4096;
        for (int i = t; i < 4096; i += 1024) dwS[i] = dw[i];
        if (t < 64) biasS[t] = db[t];
    }
    {
        const float4* E4 = (const float4*)E;
        float4* it4 = (float4*)itemsS;
        const int* hr = his + b*SS;
        for (int f = t; f < SS*16; f += 1024) {
            int s = f >> 4, c = f & 15;
            it4[s*17 + c] = E4[(size_t)hr[s]*16 + c];
        }
    }
    __syncthreads();
    if (w == 0) {
        float s = 0.f;
        for (int i = l; i < SS; i += 32) s += maskS[i];
#pragma unroll
        for (int o = 16; o; o >>= 1) s += __shfl_xor_sync(~0u, s, o);
        if (l == 0) sDen = 1.f / (s + 1e-9f);
    }

    {
        float* dwS = sc; float* biasS = sc + 4096;
        int s = t >> 2, q4 = t & 3;
        int d0 = 16*q4;
        u64 acc[8];
#pragma unroll
        for (int i = 0; i < 8; i++) acc[i] = 0ull;
#pragma unroll 4
        for (int e = 0; e < 64; e++) {
            float xe = itemsS[s*IST + e] + pos[s*DD + e];
            u64 xs = splat2(xe);
            const ulonglong2* wp = (const ulonglong2*)&dwS[e*64 + d0];
#pragma unroll
            for (int q = 0; q < 4; q++) {
                ulonglong2 wv = wp[q];
                ffma2(acc[2*q],   xs, wv.x);
                ffma2(acc[2*q+1], xs, wv.y);
            }
        }
#pragma unroll
        for (int i = 0; i < 8; i++) {
            float2 p = unpack2(acc[i]);
            int d = d0 + 2*i;
            qT[d*QST + s]     = tanhf(p.x + biasS[d]);
            qT[(d+1)*QST + s] = tanhf(p.y + biasS[d+1]);
        }
    }
    __syncthreads();

    float rs0 = 0.f, rs1 = 0.f;
    for (int g = 0; g < 4; g++) {
        int s0 = g*64;
        {
            int ty = t >> 7;
            int tx = t & 127;
            u64 acc[4][2];
#pragma unroll
            for (int i = 0; i < 4; i++) { acc[i][0] = 0ull; acc[i][1] = 0ull; }
#pragma unroll 4
            for (int e = 0; e < 64; e++) {
                const float* qe = &qT[e*QST];
                ulonglong2 a01 = *(const ulonglong2*)&qe[s0 + 8*ty];
                ulonglong2 a23 = *(const ulonglong2*)&qe[s0 + 8*ty + 4];
                float2 bf = *(const float2*)&qe[2*tx];
                u64 b0 = splat2(bf.x), b1 = splat2(bf.y);
                ffma2(acc[0][0], a01.x, b0); ffma2(acc[0][1], a01.x, b1);
                ffma2(acc[1][0], a01.y, b0); ffma2(acc[1][1], a01.y, b1);
                ffma2(acc[2][0], a23.x, b0); ffma2(acc[2][1], a23.x, b1);
                ffma2(acc[3][0], a23.y, b0); ffma2(acc[3][1], a23.y, b1);
            }
#pragma unroll
            for (int rp = 0; rp < 4; rp++) {
                float2 c0 = unpack2(acc[rp][0]);
                float2 c1 = unpack2(acc[rp][1]);
                *(float2*)&sc[(8*ty + 2*rp)*SST + 2*tx]     = make_float2(c0.x, c1.x);
                *(float2*)&sc[(8*ty + 2*rp + 1)*SST + 2*tx] = make_float2(c0.y, c1.y);
            }
        }
        __syncthreads();
        for (int rr = w; rr < 64; rr += 32) {
            int s = s0 + rr;
            if (maskS[s] == 0.f) {
                for (int c = l; c < 256; c += 32) sc[rr*SST + c] = 0.f;
            } else {
                float v[8]; float mx = FMIN2;
#pragma unroll
                for (int c = 0; c < 8; c++) {
                    float rawv = sc[rr*SST + l + 32*c] * 0.125f;
                    if (maskS[l + 32*c] == 0.f) rawv = NEGV;
                    v[c] = rawv; mx = fmaxf(mx, rawv);
                }
#pragma unroll
                for (int o = 16; o; o >>= 1) mx = fmaxf(mx, __shfl_xor_sync(~0u, mx, o));
                float sum = 0.f;
#pragma unroll
                for (int c = 0; c < 8; c++) { v[c] = expf(v[c] - mx); sum += v[c]; }
#pragma unroll
                for (int o = 16; o; o >>= 1) sum += __shfl_xor_sync(~0u, sum, o);
                float inv = 1.f / sum;
#pragma unroll
                for (int c = 0; c < 8; c++) sc[rr*SST + l + 32*c] = v[c]*inv;
            }
        }
        __syncthreads();
        {
            int ry = t >> 5;
            int rx = t & 31;
            u64 acc0 = 0ull, acc1 = 0ull;
            const float* r0p = &sc[(2*ry)*SST];
            const float* r1p = &sc[(2*ry + 1)*SST];
#pragma unroll 4
            for (int k = 0; k < 256; k += 2) {
                float2 af0 = *(const float2*)&r0p[k];
                float2 af1 = *(const float2*)&r1p[k];
                u64 bk  = *(const u64*)&itemsS[k*IST + 2*rx];
                u64 bk1 = *(const u64*)&itemsS[(k+1)*IST + 2*rx];
                ffma2(acc0, splat2(af0.x), bk);
                ffma2(acc1, splat2(af1.x), bk);
                ffma2(acc0, splat2(af0.y), bk1);
                ffma2(acc1, splat2(af1.y), bk1);
            }
            float2 u0 = unpack2(acc0), u1 = unpack2(acc1);
            float* so = &g_seq[((size_t)b*SS + s0 + 2*ry)*DD + 2*rx];
            *(float2*)so = u0;
            *(float2*)(so + DD) = u1;
            rs0 += u0.x + u1.x;
            rs1 += u0.y + u1.y;
        }
        __syncthreads();
    }
    {
        int rx = t & 31;
        atomicAdd(&colS[2*rx],   rs0);
        atomicAdd(&colS[2*rx+1], rs1);
    }
    __syncthreads();
    if (t < 64) g_mean[b*64 + t] = (colS[t] + g_posSum[t]) * sDen;
}

// ============ Tiled GEMM kernels (out[i][j] = sum_e A[i][e]*B[j][e]) ============
// 64x64 tile, 256 threads, 4x4 outputs/thread, f32x2 packed over j-pairs.
// Per-output accumulation is e-ascending single-fmaf -> bitwise == GEMV chains.

// trans scores: A=candW4 (i), B=cand0 (j); store to g_transT[j*CC + i]
__global__ void __launch_bounds__(256) k_transmm() {
    __shared__ float AS[64*68];
    __shared__ float BT[64*66];
    int t = threadIdx.x;
    int i0 = blockIdx.x*64, j0 = blockIdx.y*64;
    {
        const float4* Ag = (const float4*)g_candW4;
        float4* AS4 = (float4*)AS;
        for (int idx = t; idx < 1024; idx += 256) {
            int r = idx >> 4, f = idx & 15;
            AS4[r*17 + f] = Ag[(size_t)(i0 + r)*16 + f];
        }
        for (int idx = t; idx < 4096; idx += 256) {
            int e = idx & 63, bb = idx >> 6;
            BT[e*66 + bb] = g_cand0[(size_t)(j0 + bb)*64 + e];
        }
    }
    __syncthreads();
    int iq = t >> 4, jq = t & 15;
    u64 acc[4][2];
#pragma unroll
    for (int i = 0; i < 4; i++) { acc[i][0] = 0ull; acc[i][1] = 0ull; }
#pragma unroll 4
    for (int e4 = 0; e4 < 16; e4++) {
        float avf[16];
#pragma unroll
        for (int i = 0; i < 4; i++) {
            float4 v = *(const float4*)&AS[(iq*4 + i)*68 + e4*4];
            avf[i*4+0]=v.x; avf[i*4+1]=v.y; avf[i*4+2]=v.z; avf[i*4+3]=v.w;
        }
#pragma unroll
        for (int q = 0; q < 4; q++) {
            int e = 4*e4 + q;
            u64 m0 = *(const u64*)&BT[e*66 + jq*4];
            u64 m1 = *(const u64*)&BT[e*66 + jq*4 + 2];
#pragma unroll
            for (int i = 0; i < 4; i++) {
                u64 s = splat2(avf[i*4+q]);
                ffma2(acc[i][0], s, m0);
                ffma2(acc[i][1], s, m1);
            }
        }
    }
#pragma unroll
    for (int i = 0; i < 4; i++) {
        float2 u0 = unpack2(acc[i][0]);
        float2 u1 = unpack2(acc[i][1]);
        int ii = i0 + iq*4 + i;
        int jj = j0 + jq*4;
        g_transT[(size_t)(jj+0)*CC + ii] = u0.x;
        g_transT[(size_t)(jj+1)*CC + ii] = u0.y;
        g_transT[(size_t)(jj+2)*CC + ii] = u1.x;
        g_transT[(size_t)(jj+3)*CC + ii] = u1.y;
    }
}

// softmax over i within each row j of g_transT (identical reduction to old k_trans)
__global__ void __launch_bounds__(256) k_transsm() {
    __shared__ float red[8];
    __shared__ float bmax, bsum;
    int t = threadIdx.x, j = blockIdx.x, w = t >> 5, l = t & 31;
    float v0 = g_transT[(size_t)j*CC + t];
    float v1 = g_transT[(size_t)j*CC + t + 256];
    float m = fmaxf(v0, v1);
#pragma unroll
    for (int o = 16; o; o >>= 1) m = fmaxf(m, __shfl_xor_sync(~0u, m, o));
    if (l == 0) red[w] = m;
    __syncthreads();
    if (t == 0) { float mm = red[0]; for (int i = 1; i < 8; i++) mm = fmaxf(mm, red[i]); bmax = mm; }
    __syncthreads();
    float p0 = expf(v0 - bmax), p1 = expf(v1 - bmax);
    float s = p0 + p1;
#pragma unroll
    for (int o = 16; o; o >>= 1) s += __shfl_xor_sync(~0u, s, o);
    if (l == 0) red[w] = s;
    __syncthreads();
    if (t == 0) { float ss = 0.f; for (int i = 0; i < 8; i++) ss += red[i]; bsum = ss; }
    __syncthreads();
    float inv = 1.f / bsum;
    g_transT[(size_t)j*CC + t]       = p0 * inv;
    g_transT[(size_t)j*CC + t + 256] = p1 * inv;
}

// mh = tanh(mean @ W1): grid 64, 8 b per block
__global__ void __launch_bounds__(512) k_mh(const float* __restrict__ W1) {
    __shared__ float W1S[4096];
    __shared__ float meanS[512];
    int t = threadIdx.x;
    int b0 = blockIdx.x*8;
    for (int i = t; i < 4096; i += 512) W1S[i] = W1[i];
    meanS[t] = g_mean[b0*64 + t];
    __syncthreads();
    int bb = t >> 6, d = t & 63;
    float a = 0.f;
#pragma unroll 16
    for (int e = 0; e < 64; e++) a = fmaf(meanS[bb*64 + e], W1S[e*64 + d], a);
    g_mh[(size_t)(b0 + bb)*64 + d] = tanhf(a);
}

// L1[b][c] = cand[c] . mh[b] : A=g_cand (i=c), B=g_mh (j=b); store g_L1[b*CC + c]
__global__ void __launch_bounds__(256) k_logits1() {
    __shared__ float AS[64*68];
    __shared__ float BT[64*66];
    int t = threadIdx.x;
    int c0 = blockIdx.x*64, b0 = blockIdx.y*64;
    {
        const float4* Ag = (const float4*)g_cand;
        float4* AS4 = (float4*)AS;
        for (int idx = t; idx < 1024; idx += 256) {
            int r = idx >> 4, f = idx & 15;
            AS4[r*17 + f] = Ag[(size_t)(c0 + r)*16 + f];
        }
        for (int idx = t; idx < 4096; idx += 256) {
            int e = idx & 63, bb = idx >> 6;
            BT[e*66 + bb] = g_mh[(size_t)(b0 + bb)*64 + e];
        }
    }
    __syncthreads();
    int iq = t >> 4, jq = t & 15;
    u64 acc[4][2];
#pragma unroll
    for (int i = 0; i < 4; i++) { acc[i][0] = 0ull; acc[i][1] = 0ull; }
#pragma unroll 4
    for (int e4 = 0; e4 < 16; e4++) {
        float avf[16];
#pragma unroll
        for (int i = 0; i < 4; i++) {
            float4 v = *(const float4*)&AS[(iq*4 + i)*68 + e4*4];
            avf[i*4+0]=v.x; avf[i*4+1]=v.y; avf[i*4+2]=v.z; avf[i*4+3]=v.w;
        }
#pragma unroll
        for (int q = 0; q < 4; q++) {
            int e = 4*e4 + q;
            u64 m0 = *(const u64*)&BT[e*66 + jq*4];
            u64 m1 = *(const u64*)&BT[e*66 + jq*4 + 2];
#pragma unroll
            for (int i = 0; i < 4; i++) {
                u64 s = splat2(avf[i*4+q]);
                ffma2(acc[i][0], s, m0);
                ffma2(acc[i][1], s, m1);
            }
        }
    }
#pragma unroll
    for (int i = 0; i < 4; i++) {
        float2 u0 = unpack2(acc[i][0]);
        float2 u1 = unpack2(acc[i][1]);
        int cc = c0 + iq*4 + i;
        int bb = b0 + jq*4;
        g_L1[(size_t)(bb+0)*CC + cc] = u0.x;
        g_L1[(size_t)(bb+1)*CC + cc] = u0.y;
        g_L1[(size_t)(bb+2)*CC + cc] = u1.x;
        g_L1[(size_t)(bb+3)*CC + cc] = u1.y;
    }
}

// L2[b][t] = sum_i transT[t][i] * L1[b][i] : A=g_transT rows t, B=g_L1 rows b, k=512 in 8 chunks
__global__ void __launch_bounds__(256) k_logits2() {
    __shared__ float AS[64*68];
    __shared__ float BT[64*66];
    int t = threadIdx.x;
    int t0 = blockIdx.x*64, b0 = blockIdx.y*64;
    int iq = t >> 4, jq = t & 15;
    u64 acc[4][2];
#pragma unroll
    for (int i = 0; i < 4; i++) { acc[i][0] = 0ull; acc[i][1] = 0ull; }
    for (int ch = 0; ch < 8; ch++) {
        __syncthreads();
        {
            const float4* Ag = (const float4*)g_transT;
            float4* AS4 = (float4*)AS;
            for (int idx = t; idx < 1024; idx += 256) {
                int r = idx >> 4, f = idx & 15;
                AS4[r*17 + f] = Ag[(size_t)(t0 + r)*128 + ch*16 + f];
            }
            for (int idx = t; idx < 4096; idx += 256) {
                int e = idx & 63, bb = idx >> 6;
                BT[e*66 + bb] = g_L1[(size_t)(b0 + bb)*CC + ch*64 + e];
            }
        }
        __syncthreads();
#pragma unroll 4
        for (int e4 = 0; e4 < 16; e4++) {
            float avf[16];
#pragma unroll
            for (int i = 0; i < 4; i++) {
                float4 v = *(const float4*)&AS[(iq*4 + i)*68 + e4*4];
                avf[i*4+0]=v.x; avf[i*4+1]=v.y; avf[i*4+2]=v.z; avf[i*4+3]=v.w;
            }
#pragma unroll
            for (int q = 0; q < 4; q++) {
                int e = 4*e4 + q;
                u64 m0 = *(const u64*)&BT[e*66 + jq*4];
                u64 m1 = *(const u64*)&BT[e*66 + jq*4 + 2];
#pragma unroll
                for (int i = 0; i < 4; i++) {
                    u64 s = splat2(avf[i*4+q]);
                    ffma2(acc[i][0], s, m0);
                    ffma2(acc[i][1], s, m1);
                }
            }
        }
    }
#pragma unroll
    for (int i = 0; i < 4; i++) {
        float2 u0 = unpack2(acc[i][0]);
        float2 u1 = unpack2(acc[i][1]);
        int tt = t0 + iq*4 + i;
        int bb = b0 + jq*4;
        g_L2[(size_t)(bb+0)*CC + tt] = u0.x;
        g_L2[(size_t)(bb+1)*CC + tt] = u0.y;
        g_L2[(size_t)(bb+2)*CC + tt] = u1.x;
        g_L2[(size_t)(bb+3)*CC + tt] = u1.y;
    }
}

// ---------------- K4b: per-batch tail (top4 + multi-interest + outputs) ----------------
__global__ void __launch_bounds__(512) k_tail2(
    const float* __restrict__ E, const float* __restrict__ W1,
    const float* __restrict__ pos, const int* __restrict__ mask,
    const int* __restrict__ midb, float* __restrict__ out, long out_size)
{
    __shared__ float W1S[4096];
    __shared__ float logitsS[512];
    __shared__ float wrS[4*260];
    __shared__ float aqS[256];
    __shared__ float uebS[256];
    __shared__ float maskS[256];
    __shared__ float itemS[64];
    __shared__ float rv[16]; __shared__ int riS[16];
    __shared__ int idxS[4];
    __shared__ float dotS[4]; __shared__ int ridxS;

    int b = blockIdx.x, t = threadIdx.x, w = t >> 5, l = t & 31;

    if (t < SS) maskS[t] = (float)mask[b*SS + t];
    if (t < 64) itemS[t] = E[(size_t)midb[b]*DD + t];
    for (int i = t; i < 4096; i += 512) W1S[i] = W1[i];
    logitsS[t] = g_L2[(size_t)b*CC + t];
    __syncthreads();

    for (int p = 0; p < 4; p++) {
        float bv = logitsS[t]; int bi = t;
#pragma unroll
        for (int o = 16; o; o >>= 1) {
            float ov = __shfl_xor_sync(~0u, bv, o);
            int   oi = __shfl_xor_sync(~0u, bi, o);
            if (ov > bv || (ov == bv && oi < bi)) { bv = ov; bi = oi; }
        }
        if (l == 0) { rv[w] = bv; riS[w] = bi; }
        __syncthreads();
        if (t == 0) {
            float B2 = rv[0]; int BI = riS[0];
            for (int i = 1; i < 16; i++)
                if (rv[i] > B2 || (rv[i] == B2 && riS[i] < BI)) { B2 = rv[i]; BI = riS[i]; }
            idxS[p] = BI; logitsS[BI] = FMIN2;
        }
        __syncthreads();
    }
    if (t < 256) { int k = t >> 6, d = t & 63; aqS[t] = g_cand[(size_t)idxS[k]*64 + d]; }
    __syncthreads();

    // D: multi-interest attention (fast math OK: feeds outputs 0/1 only)
    {
        int s = t >> 1, half = t & 1;
        int d0 = 32*half;
        u64 acc[16];
#pragma unroll
        for (int i = 0; i < 16; i++) acc[i] = 0ull;
        const float4* sr4 = (const float4*)&g_seq[((size_t)b*SS + s)*DD];
        const float4* pp4 = (const float4*)&pos[s*DD];
#pragma unroll 4
        for (int e4 = 0; e4 < 16; e4++) {
            float4 sv = sr4[e4], pv = pp4[e4];
            float xs4[4];
            xs4[0] = sv.x + pv.x; xs4[1] = sv.y + pv.y;
            xs4[2] = sv.z + pv.z; xs4[3] = sv.w + pv.w;
#pragma unroll
            for (int q = 0; q < 4; q++) {
                u64 xs = splat2(xs4[q]);
                const ulonglong2* wp = (const ulonglong2*)&W1S[(4*e4+q)*64 + d0];
#pragma unroll
                for (int r = 0; r < 8; r++) {
                    ulonglong2 wv = wp[r];
                    ffma2(acc[2*r],   xs, wv.x);
                    ffma2(acc[2*r+1], xs, wv.y);
                }
            }
        }
        float ihv[32];
#pragma unroll
        for (int i = 0; i < 16; i++) {
            float2 p = unpack2(acc[i]);
            ihv[2*i]   = tanh_fast(p.x);
            ihv[2*i+1] = tanh_fast(p.y);
        }
        float wv[4];
#pragma unroll
        for (int k = 0; k < 4; k++) {
            float a = 0.f;
            const float* aq = &aqS[k*64 + d0];
#pragma unroll
            for (int i = 0; i < 32; i++) a = fmaf(ihv[i], aq[i], a);
            a += __shfl_xor_sync(~0u, a, 1);
            wv[k] = a;
        }
        if (half == 0) {
            float m = maskS[s];
#pragma unroll
            for (int k = 0; k < 4; k++)
                wrS[k*260 + s] = (m == 0.f) ? NEGV : wv[k];
        }
    }
    __syncthreads();
    if (w < 4) {
        float v[8]; float mx = FMIN2;
#pragma unroll
        for (int c = 0; c < 8; c++) { v[c] = wrS[w*260 + l + 32*c]; mx = fmaxf(mx, v[c]); }
#pragma unroll
        for (int o = 16; o; o >>= 1) mx = fmaxf(mx, __shfl_xor_sync(~0u, mx, o));
        float sum = 0.f;
#pragma unroll
        for (int c = 0; c < 8; c++) { v[c] = __expf(v[c] - mx); sum += v[c]; }
#pragma unroll
        for (int o = 16; o; o >>= 1) sum += __shfl_xor_sync(~0u, sum, o);
        float inv = 1.f / sum;
#pragma unroll
        for (int c = 0; c < 8; c++) wrS[w*260 + l + 32*c] = v[c]*inv;
    }
    __syncthreads();
    if (t < 256) {
        int k = t >> 6, d = t & 63;
        const float* wp = &wrS[k*260];
        const float* sp = &g_seq[(size_t)b*SS*DD + d];
        float a = 0.f;
#pragma unroll 8
        for (int s = 0; s < 256; s++) a = fmaf(wp[s], sp[(size_t)s*64], a);
        uebS[t] = a;
        long off = 32768 + (long)b*256 + t;
        if (off < out_size) out[off] = a;
    }
    __syncthreads();
    if (w < 4) {
        float p = uebS[w*64 + l]*itemS[l] + uebS[w*64 + l + 32]*itemS[l + 32];
#pragma unroll
        for (int o = 16; o; o >>= 1) p += __shfl_xor_sync(~0u, p, o);
        if (l == 0) dotS[w] = p;
    }
    __syncthreads();
    if (t == 0) {
        float bv2 = dotS[0]; int bi2 = 0;
        for (int k = 1; k < 4; k++) if (dotS[k] > bv2) { bv2 = dotS[k]; bi2 = k; }
        ridxS = bi2;
    }
    __syncthreads();
    if (t < 64) {
        long off = (long)b*64 + t;
        if (off < out_size) out[off] = uebS[ridxS*64 + t];
    }
    if (t < 4) {
        long off = 163840 + (long)b*4 + t;
        if (off < out_size) out[off] = (float)idxS[t];
    }
}

extern "C" void kernel_launch(void* const* d_in, const int* in_sizes, int n_in,
                              void* d_out, int out_size) {
    const float* E    = (const float*)d_in[0];
    const float* W1   = (const float*)d_in[1];
    const float* W2   = (const float*)d_in[2];
    const float* W3   = (const float*)d_in[3];
    const float* W4   = (const float*)d_in[4];
    const float* pos  = (const float*)d_in[5];
    const float* dw   = (const float*)d_in[6];
    const float* db   = (const float*)d_in[7];
    const int*   his  = (const int*)d_in[8];
    const int*   mask = (const int*)d_in[9];
    const int*   midb = (const int*)d_in[10];
    float* out = (float*)d_out;

    cudaFuncSetAttribute(k_heavy, cudaFuncAttributeMaxDynamicSharedMemorySize,
                         SM_FLOATS * (int)sizeof(float));

    k_pre<<<1, 256>>>(pos);
    k_wmean<<<1184, 256>>>(E, W2);
    k_cand<<<CC, DD>>>(W3, W1, W4);
    k_heavy<<<BB, 1024, SM_FLOATS * sizeof(float)>>>(E, pos, dw, db, his, mask);
    k_transmm<<<dim3(8,8), 256>>>();
    k_transsm<<<CC, 256>>>();
    k_mh<<<64, 512>>>(W1);
    k_logits1<<<dim3(8,8), 256>>>();
    k_logits2<<<dim3(8,8), 256>>>();
    k_tail2<<<BB, 512>>>(E, W1, pos, mask, midb, out, (long)out_size);
}

// round 17
// speedup vs baseline: 1.0553x; 1.0525x over previous
#include <cuda_runtime.h>
#include <math.h>

#define NMID 500000
#define DD 64
#define KI 4
#define CC 512
#define SS 256
#define BB 512
#define NEGV (-4294967295.0f)
#define FMIN2 (-3.402823466e38f)
#define IST 68
#define QST 264
#define SST 260
#define SM_FLOATS 51328
#define SEQ_SM_FLOATS 25728

typedef unsigned long long u64;

__device__ __forceinline__ u64 splat2(float x) {
    u64 r; asm("mov.b64 %0, {%1,%1};" : "=l"(r) : "f"(x)); return r;
}
__device__ __forceinline__ void ffma2(u64& acc, u64 a, u64 b) {
    asm("fma.rn.f32x2 %0, %1, %2, %0;" : "+l"(acc) : "l"(a), "l"(b));
}
__device__ __forceinline__ float2 unpack2(u64 v) {
    float2 f; asm("mov.b64 {%0,%1}, %2;" : "=f"(f.x), "=f"(f.y) : "l"(v)); return f;
}
__device__ __forceinline__ float tanh_fast(float x) {
    float t = __expf(2.f * x);
    return 1.f - __fdividef(2.f, t + 1.f);
}

__device__ float g_wmean[KI*DD];
__device__ float g_posSum[DD];
__device__ float g_cand0[CC*DD];
__device__ float g_cand[CC*DD];
__device__ float g_candW4[CC*DD];
__device__ float g_transT[(size_t)CC*CC];
__device__ float g_seq[(size_t)BB*SS*DD];
__device__ float g_att[(size_t)BB*SS*SS];
__device__ float g_items[(size_t)BB*SS*DD];
__device__ float g_colsum[BB*DD];
__device__ float g_den[BB];
__device__ float g_mh[BB*DD];
__device__ float g_L1[(size_t)BB*CC];
__device__ float g_L2[(size_t)BB*CC];

__global__ void k_pre(const float* __restrict__ pos) {
    int t = threadIdx.x, b = blockIdx.x;
    if (b == 0) {
        if (t < KI*DD) g_wmean[t] = 0.f;
        if (t < DD) {
            float s = 0.f;
            for (int i = 0; i < SS; i++) s += pos[i*DD + t];
            g_posSum[t] = s;
        }
    } else {
        int base = (b - 1) * 1024;
        for (int i = t; i < 1024; i += 256) g_colsum[base + i] = 0.f;
    }
}

__global__ void k_wmean(const float* __restrict__ E, const float* __restrict__ W2) {
    __shared__ float red[8*256];
    int t = threadIdx.x, l = t & 31, wi = t >> 5;
    int gw = (blockIdx.x*blockDim.x + t) >> 5;
    int TW = (gridDim.x*blockDim.x) >> 5;
    float2 w2[KI];
#pragma unroll
    for (int k = 0; k < KI; k++) {
        w2[k].x = W2[k*DD + 2*l];
        w2[k].y = W2[k*DD + 2*l + 1];
    }
    float2 acc[KI];
#pragma unroll
    for (int k = 0; k < KI; k++) acc[k] = make_float2(0.f, 0.f);
    const float2* E2 = (const float2*)E;
    for (long n = gw; n < NMID; n += TW) {
        float2 e = E2[n*32 + l];
#pragma unroll
        for (int k = 0; k < KI; k++) {
            float p = fmaf(e.x, w2[k].x, e.y*w2[k].y);
#pragma unroll
            for (int o = 16; o; o >>= 1) p += __shfl_xor_sync(~0u, p, o);
            acc[k].x = fmaf(p, e.x, acc[k].x);
            acc[k].y = fmaf(p, e.y, acc[k].y);
        }
    }
#pragma unroll
    for (int k = 0; k < KI; k++) {
        red[wi*256 + k*64 + 2*l]     = acc[k].x;
        red[wi*256 + k*64 + 2*l + 1] = acc[k].y;
    }
    __syncthreads();
    if (t < 256) {
        float s = 0.f;
#pragma unroll
        for (int w = 0; w < 8; w++) s += red[w*256 + t];
        atomicAdd(&g_wmean[t], s);
    }
}

__global__ void k_cand(const float* __restrict__ W3, const float* __restrict__ W1,
                       const float* __restrict__ W4) {
    __shared__ float row[DD];
    int d = threadIdx.x, c = blockIdx.x;
    float v = 0.f;
#pragma unroll
    for (int k = 0; k < KI; k++) v = fmaf(W3[k*CC + c], g_wmean[k*DD + d], v);
    row[d] = v;
    g_cand0[c*DD + d] = v;
    __syncthreads();
    float a = 0.f, bv = 0.f;
#pragma unroll 8
    for (int e = 0; e < DD; e++) {
        float r = row[e];
        a  = fmaf(r, W1[e*DD + d], a);
        bv = fmaf(r, W4[e*DD + d], bv);
    }
    g_cand[c*DD + d]   = tanhf(a);
    g_candW4[c*DD + d] = bv;
}

// K4a: gather + q + scores + softmax; att & items -> global
__global__ void __launch_bounds__(1024,1) k_heavy(
    const float* __restrict__ E, const float* __restrict__ pos,
    const float* __restrict__ dw, const float* __restrict__ db,
    const int* __restrict__ his, const int* __restrict__ mask)
{
    extern __shared__ float sm[];
    float* itemsS = sm;
    float* qT     = sm + 17408;
    float* sc     = sm + 34304;
    float* maskS  = sm + 50944;

    int b = blockIdx.x, t = threadIdx.x, w = t >> 5, l = t & 31;

    if (t < SS) maskS[t] = (float)mask[b*SS + t];
    {
        float* dwS = sc; float* biasS = sc + 4096;
        for (int i = t; i < 4096; i += 1024) dwS[i] = dw[i];
        if (t < 64) biasS[t] = db[t];
    }
    {
        const float4* E4 = (const float4*)E;
        float4* it4 = (float4*)itemsS;
        float4* gi4 = (float4*)g_items;
        const int* hr = his + b*SS;
        for (int f = t; f < SS*16; f += 1024) {
            int s = f >> 4, c = f & 15;
            float4 v = E4[(size_t)hr[s]*16 + c];
            it4[s*17 + c] = v;
            gi4[(size_t)b*4096 + f] = v;
        }
    }
    __syncthreads();
    if (w == 0) {
        float s = 0.f;
        for (int i = l; i < SS; i += 32) s += maskS[i];
#pragma unroll
        for (int o = 16; o; o >>= 1) s += __shfl_xor_sync(~0u, s, o);
        if (l == 0) g_den[b] = 1.f / (s + 1e-9f);
    }

    {   // B: qT = tanh((items+pos)@dense_w + b)
        float* dwS = sc; float* biasS = sc + 4096;
        int s = t >> 2, q4 = t & 3;
        int d0 = 16*q4;
        u64 acc[8];
#pragma unroll
        for (int i = 0; i < 8; i++) acc[i] = 0ull;
#pragma unroll 4
        for (int e = 0; e < 64; e++) {
            float xe = itemsS[s*IST + e] + pos[s*DD + e];
            u64 xs = splat2(xe);
            const ulonglong2* wp = (const ulonglong2*)&dwS[e*64 + d0];
#pragma unroll
            for (int q = 0; q < 4; q++) {
                ulonglong2 wv = wp[q];
                ffma2(acc[2*q],   xs, wv.x);
                ffma2(acc[2*q+1], xs, wv.y);
            }
        }
#pragma unroll
        for (int i = 0; i < 8; i++) {
            float2 p = unpack2(acc[i]);
            int d = d0 + 2*i;
            qT[d*QST + s]     = tanhf(p.x + biasS[d]);
            qT[(d+1)*QST + s] = tanhf(p.y + biasS[d+1]);
        }
    }
    __syncthreads();

    float4* att4 = (float4*)g_att;
    for (int g = 0; g < 4; g++) {
        int s0 = g*64;
        {   // C1 scores
            int ty = t >> 7;
            int tx = t & 127;
            u64 acc[4][2];
#pragma unroll
            for (int i = 0; i < 4; i++) { acc[i][0] = 0ull; acc[i][1] = 0ull; }
#pragma unroll 4
            for (int e = 0; e < 64; e++) {
                const float* qe = &qT[e*QST];
                ulonglong2 a01 = *(const ulonglong2*)&qe[s0 + 8*ty];
                ulonglong2 a23 = *(const ulonglong2*)&qe[s0 + 8*ty + 4];
                float2 bf = *(const float2*)&qe[2*tx];
                u64 b0 = splat2(bf.x), b1 = splat2(bf.y);
                ffma2(acc[0][0], a01.x, b0); ffma2(acc[0][1], a01.x, b1);
                ffma2(acc[1][0], a01.y, b0); ffma2(acc[1][1], a01.y, b1);
                ffma2(acc[2][0], a23.x, b0); ffma2(acc[2][1], a23.x, b1);
                ffma2(acc[3][0], a23.y, b0); ffma2(acc[3][1], a23.y, b1);
            }
#pragma unroll
            for (int rp = 0; rp < 4; rp++) {
                float2 c0 = unpack2(acc[rp][0]);
                float2 c1 = unpack2(acc[rp][1]);
                *(float2*)&sc[(8*ty + 2*rp)*SST + 2*tx]     = make_float2(c0.x, c1.x);
                *(float2*)&sc[(8*ty + 2*rp + 1)*SST + 2*tx] = make_float2(c0.y, c1.y);
            }
        }
        __syncthreads();
        for (int rr = w; rr < 64; rr += 32) {   // C2 softmax (exact expf)
            int s = s0 + rr;
            if (maskS[s] == 0.f) {
                for (int c = l; c < 256; c += 32) sc[rr*SST + c] = 0.f;
            } else {
                float v[8]; float mx = FMIN2;
#pragma unroll
                for (int c = 0; c < 8; c++) {
                    float rawv = sc[rr*SST + l + 32*c] * 0.125f;
                    if (maskS[l + 32*c] == 0.f) rawv = NEGV;
                    v[c] = rawv; mx = fmaxf(mx, rawv);
                }
#pragma unroll
                for (int o = 16; o; o >>= 1) mx = fmaxf(mx, __shfl_xor_sync(~0u, mx, o));
                float sum = 0.f;
#pragma unroll
                for (int c = 0; c < 8; c++) { v[c] = expf(v[c] - mx); sum += v[c]; }
#pragma unroll
                for (int o = 16; o; o >>= 1) sum += __shfl_xor_sync(~0u, sum, o);
                float inv = 1.f / sum;
#pragma unroll
                for (int c = 0; c < 8; c++) sc[rr*SST + l + 32*c] = v[c]*inv;
            }
        }
        __syncthreads();
        for (int f = t; f < 4096; f += 1024) {  // att -> global, coalesced
            int row = f >> 6, c4 = f & 63;
            float4 v = *(float4*)&sc[row*SST + 4*c4];
            att4[((size_t)b*SS + s0 + row)*64 + c4] = v;
        }
        __syncthreads();
    }
}

// K4s: seq = att @ items; FMA-bound global GEMM
__global__ void __launch_bounds__(512,2) k_seqg() {
    extern __shared__ float sm[];
    float* itemsS2 = sm;            // 256 x 68
    float* attT    = sm + 17408;    // 32 x 260

    int b = blockIdx.x, t = threadIdx.x;
    int ts = t >> 4, td = t & 15;

    {
        const float4* gi4 = (const float4*)g_items;
        float4* it4 = (float4*)itemsS2;
        for (int f = t; f < SS*16; f += 512)
            it4[(f >> 4)*17 + (f & 15)] = gi4[(size_t)b*4096 + f];
    }

    u64 acc[8][2];
#pragma unroll
    for (int i = 0; i < 8; i++) { acc[i][0] = 0ull; acc[i][1] = 0ull; }

    const float4* att4 = (const float4*)g_att;
    for (int ch = 0; ch < 8; ch++) {
        int k0 = ch * 32;
        __syncthreads();
#pragma unroll
        for (int i = 0; i < 4; i++) {
            int f = t + 512*i;
            int kf4 = f & 7;
            int s   = f >> 3;
            float4 v = att4[((size_t)b*SS + s)*64 + ch*8 + kf4];
            int sg = s >> 3, sw = s & 7;
            int slot = (sg ^ kf4) * 8 + sw;
            attT[(4*kf4 + 0)*SST + slot] = v.x;
            attT[(4*kf4 + 1)*SST + slot] = v.y;
            attT[(4*kf4 + 2)*SST + slot] = v.z;
            attT[(4*kf4 + 3)*SST + slot] = v.w;
        }
        __syncthreads();
#pragma unroll 4
        for (int kk = 0; kk < 32; kk++) {
            int slot8 = (ts ^ (kk >> 2)) * 8;
            float4 a0 = *(const float4*)&attT[kk*SST + slot8];
            float4 a1 = *(const float4*)&attT[kk*SST + slot8 + 4];
            ulonglong2 bf = *(const ulonglong2*)&itemsS2[(k0 + kk)*IST + 4*td];
            u64 s0 = splat2(a0.x), s1 = splat2(a0.y), s2 = splat2(a0.z), s3 = splat2(a0.w);
            u64 s4 = splat2(a1.x), s5 = splat2(a1.y), s6 = splat2(a1.z), s7 = splat2(a1.w);
            ffma2(acc[0][0], s0, bf.x); ffma2(acc[0][1], s0, bf.y);
            ffma2(acc[1][0], s1, bf.x); ffma2(acc[1][1], s1, bf.y);
            ffma2(acc[2][0], s2, bf.x); ffma2(acc[2][1], s2, bf.y);
            ffma2(acc[3][0], s3, bf.x); ffma2(acc[3][1], s3, bf.y);
            ffma2(acc[4][0], s4, bf.x); ffma2(acc[4][1], s4, bf.y);
            ffma2(acc[5][0], s5, bf.x); ffma2(acc[5][1], s5, bf.y);
            ffma2(acc[6][0], s6, bf.x); ffma2(acc[6][1], s6, bf.y);
            ffma2(acc[7][0], s7, bf.x); ffma2(acc[7][1], s7, bf.y);
        }
    }

    float cs0 = 0.f, cs1 = 0.f, cs2 = 0.f, cs3 = 0.f;
#pragma unroll
    for (int i = 0; i < 8; i++) {
        float2 u0 = unpack2(acc[i][0]);
        float2 u1 = unpack2(acc[i][1]);
        int s = ts*8 + i;
        *(float4*)&g_seq[((size_t)b*SS + s)*DD + 4*td] =
            make_float4(u0.x, u0.y, u1.x, u1.y);
        cs0 += u0.x; cs1 += u0.y; cs2 += u1.x; cs3 += u1.y;
    }
    atomicAdd(&g_colsum[b*DD + 4*td + 0], cs0);
    atomicAdd(&g_colsum[b*DD + 4*td + 1], cs1);
    atomicAdd(&g_colsum[b*DD + 4*td + 2], cs2);
    atomicAdd(&g_colsum[b*DD + 4*td + 3], cs3);
}

// shared 64x64 tile inner product (e-ascending, bitwise == GEMV chain)
__device__ __forceinline__ void mm_inner(const float* AS, const float* BT,
                                         int iq, int jq, u64 acc[4][2]) {
#pragma unroll 4
    for (int e4 = 0; e4 < 16; e4++) {
        float avf[16];
#pragma unroll
        for (int i = 0; i < 4; i++) {
            float4 v = *(const float4*)&AS[(iq*4 + i)*68 + e4*4];
            avf[i*4+0]=v.x; avf[i*4+1]=v.y; avf[i*4+2]=v.z; avf[i*4+3]=v.w;
        }
#pragma unroll
        for (int q = 0; q < 4; q++) {
            int e = 4*e4 + q;
            u64 m0 = *(const u64*)&BT[e*66 + jq*4];
            u64 m1 = *(const u64*)&BT[e*66 + jq*4 + 2];
#pragma unroll
            for (int i = 0; i < 4; i++) {
                u64 s = splat2(avf[i*4+q]);
                ffma2(acc[i][0], s, m0);
                ffma2(acc[i][1], s, m1);
            }
        }
    }
}

__global__ void __launch_bounds__(256) k_transmm() {
    __shared__ float AS[64*68];
    __shared__ float BT[64*66];
    int t = threadIdx.x;
    int i0 = blockIdx.x*64, j0 = blockIdx.y*64;
    {
        const float4* Ag = (const float4*)g_candW4;
        float4* AS4 = (float4*)AS;
        for (int idx = t; idx < 1024; idx += 256)
            AS4[(idx >> 4)*17 + (idx & 15)] = Ag[(size_t)(i0 + (idx >> 4))*16 + (idx & 15)];
        for (int idx = t; idx < 4096; idx += 256)
            BT[(idx & 63)*66 + (idx >> 6)] = g_cand0[(size_t)(j0 + (idx >> 6))*64 + (idx & 63)];
    }
    __syncthreads();
    int iq = t >> 4, jq = t & 15;
    u64 acc[4][2];
#pragma unroll
    for (int i = 0; i < 4; i++) { acc[i][0] = 0ull; acc[i][1] = 0ull; }
    mm_inner(AS, BT, iq, jq, acc);
#pragma unroll
    for (int i = 0; i < 4; i++) {
        float2 u0 = unpack2(acc[i][0]);
        float2 u1 = unpack2(acc[i][1]);
        int ii = i0 + iq*4 + i, jj = j0 + jq*4;
        g_transT[(size_t)(jj+0)*CC + ii] = u0.x;
        g_transT[(size_t)(jj+1)*CC + ii] = u0.y;
        g_transT[(size_t)(jj+2)*CC + ii] = u1.x;
        g_transT[(size_t)(jj+3)*CC + ii] = u1.y;
    }
}

__global__ void __launch_bounds__(256) k_transsm() {
    __shared__ float red[8];
    __shared__ float bmax, bsum;
    int t = threadIdx.x, j = blockIdx.x, w = t >> 5, l = t & 31;
    float v0 = g_transT[(size_t)j*CC + t];
    float v1 = g_transT[(size_t)j*CC + t + 256];
    float m = fmaxf(v0, v1);
#pragma unroll
    for (int o = 16; o; o >>= 1) m = fmaxf(m, __shfl_xor_sync(~0u, m, o));
    if (l == 0) red[w] = m;
    __syncthreads();
    if (t == 0) { float mm = red[0]; for (int i = 1; i < 8; i++) mm = fmaxf(mm, red[i]); bmax = mm; }
    __syncthreads();
    float p0 = expf(v0 - bmax), p1 = expf(v1 - bmax);
    float s = p0 + p1;
#pragma unroll
    for (int o = 16; o; o >>= 1) s += __shfl_xor_sync(~0u, s, o);
    if (l == 0) red[w] = s;
    __syncthreads();
    if (t == 0) { float ss = 0.f; for (int i = 0; i < 8; i++) ss += red[i]; bsum = ss; }
    __syncthreads();
    float inv = 1.f / bsum;
    g_transT[(size_t)j*CC + t]       = p0 * inv;
    g_transT[(size_t)j*CC + t + 256] = p1 * inv;
}

__global__ void __launch_bounds__(512) k_mh(const float* __restrict__ W1) {
    __shared__ float W1S[4096];
    __shared__ float meanS[512];
    int t = threadIdx.x;
    int b0 = blockIdx.x*8;
    for (int i = t; i < 4096; i += 512) W1S[i] = W1[i];
    {
        int bb = t >> 6, d = t & 63;
        meanS[t] = (g_colsum[(b0 + bb)*DD + d] + g_posSum[d]) * g_den[b0 + bb];
    }
    __syncthreads();
    int bb = t >> 6, d = t & 63;
    float a = 0.f;
#pragma unroll 16
    for (int e = 0; e < 64; e++) a = fmaf(meanS[bb*64 + e], W1S[e*64 + d], a);
    g_mh[(size_t)(b0 + bb)*64 + d] = tanhf(a);
}

__global__ void __launch_bounds__(256) k_logits1() {
    __shared__ float AS[64*68];
    __shared__ float BT[64*66];
    int t = threadIdx.x;
    int c0 = blockIdx.x*64, b0 = blockIdx.y*64;
    {
        const float4* Ag = (const float4*)g_cand;
        float4* AS4 = (float4*)AS;
        for (int idx = t; idx < 1024; idx += 256)
            AS4[(idx >> 4)*17 + (idx & 15)] = Ag[(size_t)(c0 + (idx >> 4))*16 + (idx & 15)];
        for (int idx = t; idx < 4096; idx += 256)
            BT[(idx & 63)*66 + (idx >> 6)] = g_mh[(size_t)(b0 + (idx >> 6))*64 + (idx & 63)];
    }
    __syncthreads();
    int iq = t >> 4, jq = t & 15;
    u64 acc[4][2];
#pragma unroll
    for (int i = 0; i < 4; i++) { acc[i][0] = 0ull; acc[i][1] = 0ull; }
    mm_inner(AS, BT, iq, jq, acc);
#pragma unroll
    for (int i = 0; i < 4; i++) {
        float2 u0 = unpack2(acc[i][0]);
        float2 u1 = unpack2(acc[i][1]);
        int cc = c0 + iq*4 + i, bb = b0 + jq*4;
        g_L1[(size_t)(bb+0)*CC + cc] = u0.x;
        g_L1[(size_t)(bb+1)*CC + cc] = u0.y;
        g_L1[(size_t)(bb+2)*CC + cc] = u1.x;
        g_L1[(size_t)(bb+3)*CC + cc] = u1.y;
    }
}

__global__ void __launch_bounds__(256) k_logits2() {
    __shared__ float AS[64*68];
    __shared__ float BT[64*66];
    int t = threadIdx.x;
    int t0 = blockIdx.x*64, b0 = blockIdx.y*64;
    int iq = t >> 4, jq = t & 15;
    u64 acc[4][2];
#pragma unroll
    for (int i = 0; i < 4; i++) { acc[i][0] = 0ull; acc[i][1] = 0ull; }
    for (int ch = 0; ch < 8; ch++) {
        __syncthreads();
        {
            const float4* Ag = (const float4*)g_transT;
            float4* AS4 = (float4*)AS;
            for (int idx = t; idx < 1024; idx += 256)
                AS4[(idx >> 4)*17 + (idx & 15)] =
                    Ag[(size_t)(t0 + (idx >> 4))*128 + ch*16 + (idx & 15)];
            for (int idx = t; idx < 4096; idx += 256)
                BT[(idx & 63)*66 + (idx >> 6)] =
                    g_L1[(size_t)(b0 + (idx >> 6))*CC + ch*64 + (idx & 63)];
        }
        __syncthreads();
        mm_inner(AS, BT, iq, jq, acc);
    }
#pragma unroll
    for (int i = 0; i < 4; i++) {
        float2 u0 = unpack2(acc[i][0]);
        float2 u1 = unpack2(acc[i][1]);
        int tt = t0 + iq*4 + i, bb = b0 + jq*4;
        g_L2[(size_t)(bb+0)*CC + tt] = u0.x;
        g_L2[(size_t)(bb+1)*CC + tt] = u0.y;
        g_L2[(size_t)(bb+2)*CC + tt] = u1.x;
        g_L2[(size_t)(bb+3)*CC + tt] = u1.y;
    }
}

__global__ void __launch_bounds__(512) k_tail2(
    const float* __restrict__ E, const float* __restrict__ W1,
    const float* __restrict__ pos, const int* __restrict__ mask,
    const int* __restrict__ midb, float* __restrict__ out, long out_size)
{
    __shared__ float W1S[4096];
    __shared__ float logitsS[512];
    __shared__ float wrS[4*260];
    __shared__ float aqS[256];
    __shared__ float uebS[256];
    __shared__ float maskS[256];
    __shared__ float itemS[64];
    __shared__ float rv[16]; __shared__ int riS[16];
    __shared__ int idxS[4];
    __shared__ float dotS[4]; __shared__ int ridxS;

    int b = blockIdx.x, t = threadIdx.x, w = t >> 5, l = t & 31;

    if (t < SS) maskS[t] = (float)mask[b*SS + t];
    if (t < 64) itemS[t] = E[(size_t)midb[b]*DD + t];
    for (int i = t; i < 4096; i += 512) W1S[i] = W1[i];
    logitsS[t] = g_L2[(size_t)b*CC + t];
    __syncthreads();

    for (int p = 0; p < 4; p++) {
        float bv = logitsS[t]; int bi = t;
#pragma unroll
        for (int o = 16; o; o >>= 1) {
            float ov = __shfl_xor_sync(~0u, bv, o);
            int   oi = __shfl_xor_sync(~0u, bi, o);
            if (ov > bv || (ov == bv && oi < bi)) { bv = ov; bi = oi; }
        }
        if (l == 0) { rv[w] = bv; riS[w] = bi; }
        __syncthreads();
        if (t == 0) {
            float B2 = rv[0]; int BI = riS[0];
            for (int i = 1; i < 16; i++)
                if (rv[i] > B2 || (rv[i] == B2 && riS[i] < BI)) { B2 = rv[i]; BI = riS[i]; }
            idxS[p] = BI; logitsS[BI] = FMIN2;
        }
        __syncthreads();
    }
    if (t < 256) { int k = t >> 6, d = t & 63; aqS[t] = g_cand[(size_t)idxS[k]*64 + d]; }
    __syncthreads();

    {
        int s = t >> 1, half = t & 1;
        int d0 = 32*half;
        u64 acc[16];
#pragma unroll
        for (int i = 0; i < 16; i++) acc[i] = 0ull;
        const float4* sr4 = (const float4*)&g_seq[((size_t)b*SS + s)*DD];
        const float4* pp4 = (const float4*)&pos[s*DD];
#pragma unroll 4
        for (int e4 = 0; e4 < 16; e4++) {
            float4 sv = sr4[e4], pv = pp4[e4];
            float xs4[4];
            xs4[0] = sv.x + pv.x; xs4[1] = sv.y + pv.y;
            xs4[2] = sv.z + pv.z; xs4[3] = sv.w + pv.w;
#pragma unroll
            for (int q = 0; q < 4; q++) {
                u64 xs = splat2(xs4[q]);
                const ulonglong2* wp = (const ulonglong2*)&W1S[(4*e4+q)*64 + d0];
#pragma unroll
                for (int r = 0; r < 8; r++) {
                    ulonglong2 wv = wp[r];
                    ffma2(acc[2*r],   xs, wv.x);
                    ffma2(acc[2*r+1], xs, wv.y);
                }
            }
        }
        float ihv[32];
#pragma unroll
        for (int i = 0; i < 16; i++) {
            float2 p = unpack2(acc[i]);
            ihv[2*i]   = tanh_fast(p.x);
            ihv[2*i+1] = tanh_fast(p.y);
        }
        float wv[4];
#pragma unroll
        for (int k = 0; k < 4; k++) {
            float a = 0.f;
            const float* aq = &aqS[k*64 + d0];
#pragma unroll
            for (int i = 0; i < 32; i++) a = fmaf(ihv[i], aq[i], a);
            a += __shfl_xor_sync(~0u, a, 1);
            wv[k] = a;
        }
        if (half == 0) {
            float m = maskS[s];
#pragma unroll
            for (int k = 0; k < 4; k++)
                wrS[k*260 + s] = (m == 0.f) ? NEGV : wv[k];
        }
    }
    __syncthreads();
    if (w < 4) {
        float v[8]; float mx = FMIN2;
#pragma unroll
        for (int c = 0; c < 8; c++) { v[c] = wrS[w*260 + l + 32*c]; mx = fmaxf(mx, v[c]); }
#pragma unroll
        for (int o = 16; o; o >>= 1) mx = fmaxf(mx, __shfl_xor_sync(~0u, mx, o));
        float sum = 0.f;
#pragma unroll
        for (int c = 0; c < 8; c++) { v[c] = __expf(v[c] - mx); sum += v[c]; }
#pragma unroll
        for (int o = 16; o; o >>= 1) sum += __shfl_xor_sync(~0u, sum, o);
        float inv = 1.f / sum;
#pragma unroll
        for (int c = 0; c < 8; c++) wrS[w*260 + l + 32*c] = v[c]*inv;
    }
    __syncthreads();
    if (t < 256) {
        int k = t >> 6, d = t & 63;
        const float* wp = &wrS[k*260];
        const float* sp = &g_seq[(size_t)b*SS*DD + d];
        float a = 0.f;
#pragma unroll 8
        for (int s = 0; s < 256; s++) a = fmaf(wp[s], sp[(size_t)s*64], a);
        uebS[t] = a;
        long off = 32768 + (long)b*256 + t;
        if (off < out_size) out[off] = a;
    }
    __syncthreads();
    if (w < 4) {
        float p = uebS[w*64 + l]*itemS[l] + uebS[w*64 + l + 32]*itemS[l + 32];
#pragma unroll
        for (int o = 16; o; o >>= 1) p += __shfl_xor_sync(~0u, p, o);
        if (l == 0) dotS[w] = p;
    }
    __syncthreads();
    if (t == 0) {
        float bv2 = dotS[0]; int bi2 = 0;
        for (int k = 1; k < 4; k++) if (dotS[k] > bv2) { bv2 = dotS[k]; bi2 = k; }
        ridxS = bi2;
    }
    __syncthreads();
    if (t < 64) {
        long off = (long)b*64 + t;
        if (off < out_size) out[off] = uebS[ridxS*64 + t];
    }
    if (t < 4) {
        long off = 163840 + (long)b*4 + t;
        if (off < out_size) out[off] = (float)idxS[t];
    }
}

extern "C" void kernel_launch(void* const* d_in, const int* in_sizes, int n_in,
                              void* d_out, int out_size) {
    const float* E    = (const float*)d_in[0];
    const float* W1   = (const float*)d_in[1];
    const float* W2   = (const float*)d_in[2];
    const float* W3   = (const float*)d_in[3];
    const float* W4   = (const float*)d_in[4];
    const float* pos  = (const float*)d_in[5];
    const float* dw   = (const float*)d_in[6];
    const float* db   = (const float*)d_in[7];
    const int*   his  = (const int*)d_in[8];
    const int*   mask = (const int*)d_in[9];
    const int*   midb = (const int*)d_in[10];
    float* out = (float*)d_out;

    cudaFuncSetAttribute(k_heavy, cudaFuncAttributeMaxDynamicSharedMemorySize,
                         SM_FLOATS * (int)sizeof(float));
    cudaFuncSetAttribute(k_seqg, cudaFuncAttributeMaxDynamicSharedMemorySize,
                         SEQ_SM_FLOATS * (int)sizeof(float));

    k_pre<<<33, 256>>>(pos);
    k_wmean<<<1184, 256>>>(E, W2);
    k_cand<<<CC, DD>>>(W3, W1, W4);
    k_heavy<<<BB, 1024, SM_FLOATS * sizeof(float)>>>(E, pos, dw, db, his, mask);
    k_seqg<<<BB, 512, SEQ_SM_FLOATS * sizeof(float)>>>();
    k_transmm<<<dim3(8,8), 256>>>();
    k_transsm<<<CC, 256>>>();
    k_mh<<<64, 512>>>(W1);
    k_logits1<<<dim3(8,8), 256>>>();
    k_logits2<<<dim3(8,8), 256>>>();
    k_tail2<<<BB, 512>>>(E, W1, pos, mask, midb, out, (long)out_size);
}